// round 1
// baseline (speedup 1.0000x reference)
#include <cuda_runtime.h>
#include <cstdint>

#define TMAX 1280

// Precomputed per-target data (setup kernel fills these each call; deterministic).
__device__ float4 g_txyxy[TMAX];   // xyxy
__device__ float2 g_tal[TMAX];     // x = area, y = label bits (int)

__device__ __forceinline__ float frcp(float x) {
    float r;
    asm("rcp.approx.f32 %0, %1;" : "=f"(r) : "f"(x));
    return r;
}

// Converts target boxes cxcywh -> xyxy + area, and normalizes labels.
// Detects whether the label buffer is int64 or int32: if int64 (labels < 91),
// every odd 32-bit word is zero; genuine int32 label data cannot be all-zero
// at odd positions for random labels in [0,91).
__global__ void setup_kernel(const float4* __restrict__ tboxes,
                             const int* __restrict__ lraw, int m) {
    __shared__ int is64;
    if (threadIdx.x == 0) is64 = 1;
    __syncthreads();
    for (int t = threadIdx.x; t < m / 2; t += blockDim.x)
        if (lraw[2 * t + 1] != 0) is64 = 0;   // benign race, single value
    __syncthreads();
    int f = is64;
    for (int j = threadIdx.x; j < m; j += blockDim.x) {
        float4 b = tboxes[j];
        float hw = 0.5f * b.z, hh = 0.5f * b.w;
        float4 t;
        t.x = b.x - hw; t.y = b.y - hh;
        t.z = b.x + hw; t.w = b.y + hh;
        g_txyxy[j] = t;
        int lab = f ? lraw[2 * j] : lraw[j];
        float2 al;
        al.x = (t.z - t.x) * (t.w - t.y);   // area from xyxy, matching reference
        al.y = __int_as_float(lab);
        g_tal[j] = al;
    }
}

// Each block: 16 rows (queries) x full M columns (targets).
// Thread layout: ty = tid>>6 picks a 4-row group, tx = tid&63 a column lane.
// Each thread computes 4 rows x (M/64) columns; query data lives in registers.
__global__ void __launch_bounds__(256)
cost_kernel(const float* __restrict__ scores,
            const float4* __restrict__ boxes,
            const float4* __restrict__ tboxes,
            float* __restrict__ out,
            int rows, int C, int m) {
    int tid = threadIdx.x;
    int tx = tid & 63;
    int ty = tid >> 6;
    int row0 = blockIdx.x * 16 + ty * 4;

    float qcx[4], qcy[4], qw[4], qh[4];
    float qx0[4], qy0[4], qx1[4], qy1[4], qa[4];
    const float* srow[4];
    float* orow[4];

#pragma unroll
    for (int k = 0; k < 4; k++) {
        int r = row0 + k;
        if (r > rows - 1) r = rows - 1;           // safe clamp (rows % 16 == 0 here)
        float4 bb = __ldg(boxes + r);
        qcx[k] = bb.x; qcy[k] = bb.y; qw[k] = bb.z; qh[k] = bb.w;
        float hw = 0.5f * bb.z, hh = 0.5f * bb.w;
        qx0[k] = bb.x - hw; qy0[k] = bb.y - hh;
        qx1[k] = bb.x + hw; qy1[k] = bb.y + hh;
        qa[k] = (qx1[k] - qx0[k]) * (qy1[k] - qy0[k]);
        srow[k] = scores + (size_t)r * C;
        orow[k] = out + (size_t)r * m + tx;
    }

    int nj = m >> 6;
#pragma unroll 4
    for (int jj = 0; jj < nj; jj++) {
        int j = tx + (jj << 6);
        float4 t  = __ldg(g_txyxy + j);    // target xyxy
        float4 tc = __ldg(tboxes + j);     // target cxcywh
        float2 al = __ldg(g_tal + j);
        float ta = al.x;
        int lab = __float_as_int(al.y);

#pragma unroll
        for (int k = 0; k < 4; k++) {
            float sc = __ldg(srow[k] + lab);

            // L1 on cxcywh (abs folds into operand modifiers)
            float l1 = fabsf(qcx[k] - tc.x) + fabsf(qcy[k] - tc.y)
                     + fabsf(qw[k] - tc.z) + fabsf(qh[k] - tc.w);

            // intersection
            float ltx = fmaxf(qx0[k], t.x), lty = fmaxf(qy0[k], t.y);
            float rbx = fminf(qx1[k], t.z), rby = fminf(qy1[k], t.w);
            float iw = fmaxf(rbx - ltx, 0.0f), ih = fmaxf(rby - lty, 0.0f);
            float inter = iw * ih;
            float uni = qa[k] + ta - inter;

            // enclosing box
            float ex0 = fminf(qx0[k], t.x), ey0 = fminf(qy0[k], t.y);
            float ex1 = fmaxf(qx1[k], t.z), ey1 = fmaxf(qy1[k], t.w);
            float ae = (ex1 - ex0) * (ey1 - ey0);

            // giou = inter/uni + uni/ae - 1
            // cost = 5*l1 - sc - 2*giou = 5*l1 + (2 - sc) - 2*(inter/uni + uni/ae)
            float s = fmaf(uni, frcp(ae), inter * frcp(uni));
            float c = fmaf(5.0f, l1, 2.0f - sc);
            c = fmaf(-2.0f, s, c);

            orow[k][(size_t)(jj << 6)] = c;
        }
    }
}

extern "C" void kernel_launch(void* const* d_in, const int* in_sizes, int n_in,
                              void* d_out, int out_size) {
    const float* scores  = (const float*)d_in[0];
    const float4* boxes  = (const float4*)d_in[1];
    const int*   labraw  = (const int*)d_in[2];
    const float4* tboxes = (const float4*)d_in[3];
    float* out = (float*)d_out;

    int rows = in_sizes[1] / 4;   // b*n = 9600
    int m    = in_sizes[3] / 4;   // 1280
    int C    = in_sizes[0] / rows; // 91

    setup_kernel<<<1, 512>>>(tboxes, labraw, m);
    int blocks = (rows + 15) / 16;
    cost_kernel<<<blocks, 256>>>(scores, boxes, tboxes, out, rows, C, m);
}

// round 2
// speedup vs baseline: 1.1059x; 1.1059x over previous
#include <cuda_runtime.h>
#include <cstdint>

#define TMAX 1280

// Precomputed per-target data (setup kernel fills these each call; deterministic).
__device__ float4 g_txyxy[TMAX];   // xyxy
__device__ float2 g_tal[TMAX];     // x = area, y = label bits (int)

__device__ __forceinline__ float frcp(float x) {
    float r;
    asm("rcp.approx.f32 %0, %1;" : "=f"(r) : "f"(x));
    return r;
}

// Converts target boxes cxcywh -> xyxy + area, and normalizes labels.
// Detects int64 vs int32 label buffer: for int64 labels < 91, every odd
// 32-bit word is zero.
__global__ void setup_kernel(const float4* __restrict__ tboxes,
                             const int* __restrict__ lraw, int m) {
    __shared__ int is64;
    if (threadIdx.x == 0) is64 = 1;
    __syncthreads();
    for (int t = threadIdx.x; t < m / 2; t += blockDim.x)
        if (lraw[2 * t + 1] != 0) is64 = 0;   // benign race, single value
    __syncthreads();
    int f = is64;
    for (int j = threadIdx.x; j < m; j += blockDim.x) {
        float4 b = tboxes[j];
        float hw = 0.5f * b.z, hh = 0.5f * b.w;
        float4 t;
        t.x = b.x - hw; t.y = b.y - hh;
        t.z = b.x + hw; t.w = b.y + hh;
        g_txyxy[j] = t;
        int lab = f ? lraw[2 * j] : lraw[j];
        float2 al;
        al.x = (t.z - t.x) * (t.w - t.y);
        al.y = __int_as_float(lab);
        g_tal[j] = al;
    }
}

// ---------------------------------------------------------------------------
// Fast path: specialized on C=91, M=1280, rows % 16 == 0.
// Block = 256 threads = 16 rows x 64 column-lanes; each thread: 4 rows x 20
// column steps. All loop offsets are compile-time immediates.
// ---------------------------------------------------------------------------
__global__ void __launch_bounds__(256)
cost_kernel_fast(const float* __restrict__ scores,
                 const float4* __restrict__ boxes,
                 const float4* __restrict__ tboxes,
                 float* __restrict__ out) {
    constexpr int C = 91;
    constexpr int M = 1280;
    constexpr int NJ = M / 64;   // 20

    int tid = threadIdx.x;
    int tx = tid & 63;
    int ty = tid >> 6;
    int row0 = blockIdx.x * 16 + ty * 4;

    float qcx[4], qcy[4], qw[4], qh[4];
    float qx0[4], qy0[4], qx1[4], qy1[4], qa[4];

#pragma unroll
    for (int k = 0; k < 4; k++) {
        float4 bb = __ldg(boxes + row0 + k);
        qcx[k] = bb.x; qcy[k] = bb.y; qw[k] = bb.z; qh[k] = bb.w;
        float hw = 0.5f * bb.z, hh = 0.5f * bb.w;
        qx0[k] = bb.x - hw; qy0[k] = bb.y - hh;
        qx1[k] = bb.x + hw; qy1[k] = bb.y + hh;
        qa[k] = (qx1[k] - qx0[k]) * (qy1[k] - qy0[k]);
    }

    const float* sp = scores + row0 * C;                  // row k at sp + k*C (imm)
    float* op = out + (size_t)row0 * M + tx;              // store at op + k*M + jj*64 (imm)
    const float4* tx4 = g_txyxy + tx;
    const float4* tc4 = tboxes + tx;
    const float2* ta2 = g_tal + tx;

#pragma unroll
    for (int jj = 0; jj < NJ; jj++) {
        float4 t  = __ldg(tx4 + jj * 64);     // target xyxy
        float4 tc = __ldg(tc4 + jj * 64);     // target cxcywh
        float2 al = __ldg(ta2 + jj * 64);     // area, label
        float ta = al.x;
        const float* sa = sp + __float_as_int(al.y);   // one IMAD per jj

#pragma unroll
        for (int k = 0; k < 4; k++) {
            float sc = __ldg(sa + k * C);     // immediate-offset gather

            float l1 = fabsf(qcx[k] - tc.x) + fabsf(qcy[k] - tc.y)
                     + fabsf(qw[k] - tc.z) + fabsf(qh[k] - tc.w);

            float ltx = fmaxf(qx0[k], t.x), lty = fmaxf(qy0[k], t.y);
            float rbx = fminf(qx1[k], t.z), rby = fminf(qy1[k], t.w);
            float iw = fmaxf(rbx - ltx, 0.0f), ih = fmaxf(rby - lty, 0.0f);
            float inter = iw * ih;
            float uni = qa[k] + ta - inter;

            float ex0 = fminf(qx0[k], t.x), ey0 = fminf(qy0[k], t.y);
            float ex1 = fmaxf(qx1[k], t.z), ey1 = fmaxf(qy1[k], t.w);
            float ae = (ex1 - ex0) * (ey1 - ey0);

            // cost = 5*l1 + (2 - sc) - 2*(inter/uni + uni/ae)
            float s = fmaf(uni, frcp(ae), inter * frcp(uni));
            float c = fmaf(5.0f, l1, 2.0f - sc);
            c = fmaf(-2.0f, s, c);

            op[k * M + jj * 64] = c;
        }
    }
}

// ---------------------------------------------------------------------------
// Generic fallback (round-1 kernel) for unexpected shapes.
// ---------------------------------------------------------------------------
__global__ void __launch_bounds__(256)
cost_kernel(const float* __restrict__ scores,
            const float4* __restrict__ boxes,
            const float4* __restrict__ tboxes,
            float* __restrict__ out,
            int rows, int C, int m) {
    int tid = threadIdx.x;
    int tx = tid & 63;
    int ty = tid >> 6;
    int row0 = blockIdx.x * 16 + ty * 4;

    float qcx[4], qcy[4], qw[4], qh[4];
    float qx0[4], qy0[4], qx1[4], qy1[4], qa[4];
    const float* srow[4];
    float* orow[4];

#pragma unroll
    for (int k = 0; k < 4; k++) {
        int r = row0 + k;
        if (r > rows - 1) r = rows - 1;
        float4 bb = __ldg(boxes + r);
        qcx[k] = bb.x; qcy[k] = bb.y; qw[k] = bb.z; qh[k] = bb.w;
        float hw = 0.5f * bb.z, hh = 0.5f * bb.w;
        qx0[k] = bb.x - hw; qy0[k] = bb.y - hh;
        qx1[k] = bb.x + hw; qy1[k] = bb.y + hh;
        qa[k] = (qx1[k] - qx0[k]) * (qy1[k] - qy0[k]);
        srow[k] = scores + (size_t)r * C;
        orow[k] = out + (size_t)r * m + tx;
    }

    int nj = m >> 6;
    for (int jj = 0; jj < nj; jj++) {
        int j = tx + (jj << 6);
        if (j >= m) break;
        float4 t  = __ldg(g_txyxy + j);
        float4 tc = __ldg(tboxes + j);
        float2 al = __ldg(g_tal + j);
        float ta = al.x;
        int lab = __float_as_int(al.y);

#pragma unroll
        for (int k = 0; k < 4; k++) {
            float sc = __ldg(srow[k] + lab);
            float l1 = fabsf(qcx[k] - tc.x) + fabsf(qcy[k] - tc.y)
                     + fabsf(qw[k] - tc.z) + fabsf(qh[k] - tc.w);
            float ltx = fmaxf(qx0[k], t.x), lty = fmaxf(qy0[k], t.y);
            float rbx = fminf(qx1[k], t.z), rby = fminf(qy1[k], t.w);
            float iw = fmaxf(rbx - ltx, 0.0f), ih = fmaxf(rby - lty, 0.0f);
            float inter = iw * ih;
            float uni = qa[k] + ta - inter;
            float ex0 = fminf(qx0[k], t.x), ey0 = fminf(qy0[k], t.y);
            float ex1 = fmaxf(qx1[k], t.z), ey1 = fmaxf(qy1[k], t.w);
            float ae = (ex1 - ex0) * (ey1 - ey0);
            float s = fmaf(uni, frcp(ae), inter * frcp(uni));
            float c = fmaf(5.0f, l1, 2.0f - sc);
            c = fmaf(-2.0f, s, c);
            orow[k][(size_t)(jj << 6)] = c;
        }
    }
}

extern "C" void kernel_launch(void* const* d_in, const int* in_sizes, int n_in,
                              void* d_out, int out_size) {
    const float* scores  = (const float*)d_in[0];
    const float4* boxes  = (const float4*)d_in[1];
    const int*   labraw  = (const int*)d_in[2];
    const float4* tboxes = (const float4*)d_in[3];
    float* out = (float*)d_out;

    int rows = in_sizes[1] / 4;      // b*n = 9600
    int m    = in_sizes[3] / 4;      // 1280
    int C    = in_sizes[0] / rows;   // 91

    setup_kernel<<<1, 512>>>(tboxes, labraw, m);

    if (C == 91 && m == 1280 && (rows % 16) == 0) {
        cost_kernel_fast<<<rows / 16, 256>>>(scores, boxes, tboxes, out);
    } else {
        int blocks = (rows + 15) / 16;
        cost_kernel<<<blocks, 256>>>(scores, boxes, tboxes, out, rows, C, m);
    }
}